// round 6
// baseline (speedup 1.0000x reference)
#include <cuda_runtime.h>
#include <math.h>
#include <stdint.h>

#define N_PTS 32768
#define D_DIM 128
#define K_CB  1024
#define ND    (N_PTS*D_DIM)        /* 4194304  */
#define NK    ((size_t)N_PTS*K_CB) /* 33554432 */

/* ---------------- persistent device scratch (no allocs allowed) ------------- */
__device__ float     g_xn[ND];            /* normalized x          16 MB  */
__device__ float     g_cn[K_CB*D_DIM];    /* normalized codebook   512 KB */
__device__ float     g_cos[N_PTS*K_CB];   /* cosine sims           134 MB */
__device__ double    g_u1[K_CB];          /* row-sum iter 1               */
__device__ double    g_u2[K_CB];          /* row-sum iter 2               */
__device__ double    g_u3[K_CB];          /* row-sum iter 3               */
__device__ double    g_a[K_CB];           /* row scaling factor           */
__device__ long long g_afix[K_CB];        /* log2(a3)*2^20 fixed point    */
__device__ unsigned  g_omin, g_omax;      /* ordered-uint encoded min/max */
__device__ double    g_loss;              /* loss accumulator             */
__device__ int       g_idx[N_PTS];        /* argmax indices               */

/* ---------------- helpers --------------------------------------------------- */
__device__ __forceinline__ unsigned ford(float f) {
    unsigned u = __float_as_uint(f);
    return (u & 0x80000000u) ? ~u : (u | 0x80000000u);
}
__device__ __forceinline__ float funord(unsigned u) {
    return (u & 0x80000000u) ? __uint_as_float(u ^ 0x80000000u)
                             : __uint_as_float(~u);
}

__device__ __forceinline__ void midamp(float& mid, float& amp) {
    float cmin = funord(g_omin), cmax = funord(g_omax);
    float dmax = (1.0f - cmin) / 0.2f;
    float dmin = (1.0f - cmax) / 0.2f;
    mid = (dmax + dmin) / 2.0f;
    amp = fmaxf(dmax - mid + 1e-5f, 1e-5f);
}

/* Cd = -log2(e)/0.005 split into two floats */
#define CD_FULL (-288.53900817779268)
#define CHI ((float)CD_FULL)
#define CLO ((float)(CD_FULL - (double)(float)CD_FULL))

/* f32 chain identical to the passing kernel (bit-exact),
   then t2 = dc*Cd as a two-float product. */
__device__ __forceinline__ void t2_split(float c, float mid, float amp,
                                         float& hi, float& lo) {
    float t  = 1.0f - c;
    float d  = t / 0.2f;
    float dc = (d - mid) / amp;
    hi = dc * CHI;
    lo = fmaf(dc, CHI, -hi);
    lo = fmaf(dc, CLO, lo);
}

/* E = 2^t2 with zero fp64 arithmetic. rel err ~2.4e-7 */
__device__ __forceinline__ double calcE(float c, float mid, float amp) {
    float hi, lo;
    t2_split(c, mid, amp, hi, lo);
    float big = hi + 12582912.0f;
    int   nn  = __float_as_int(big) - __float_as_int(12582912.0f);
    float nnf = big - 12582912.0f;
    float f   = (hi - nnf) + lo;
    float p   = exp2f(f);
    unsigned long long eb =
        ((unsigned long long)__float_as_uint(p) << 29) +
        ((unsigned long long)(unsigned)(896 + nn) << 52);
    return __longlong_as_double((long long)eb);
}

/* ---------------- kernels --------------------------------------------------- */

__global__ void k_init() {
    int i = threadIdx.x;
    g_u1[i] = 0.0; g_u2[i] = 0.0; g_u3[i] = 0.0;
    if (i == 0) { g_omin = 0xFFFFFFFFu; g_omax = 0u; g_loss = 0.0; }
}

/* L2 normalize rows of length 128; one warp per row */
__global__ void k_norm(const float* __restrict__ in, int rows, int isX) {
    int w    = (blockIdx.x * blockDim.x + threadIdx.x) >> 5;
    int lane = threadIdx.x & 31;
    if (w >= rows) return;
    float* out = isX ? g_xn : g_cn;
    const float* r = in + (size_t)w * D_DIM;
    float v0 = r[lane], v1 = r[lane + 32], v2 = r[lane + 64], v3 = r[lane + 96];
    float s = v0 * v0 + v1 * v1 + v2 * v2 + v3 * v3;
    #pragma unroll
    for (int off = 16; off; off >>= 1) s += __shfl_xor_sync(0xFFFFFFFFu, s, off);
    float den = fmaxf(sqrtf(s), 1e-12f);
    float* o = out + (size_t)w * D_DIM;
    o[lane]      = v0 / den;
    o[lane + 32] = v1 / den;
    o[lane + 64] = v2 / den;
    o[lane + 96] = v3 / den;
}

/* cos[n,k] = xn[n,:] . cn[k,:] — 128x128 tile, 8x8/thread, 2 CTA/SM.
   Pad 132 floats per row: 528B row stride (16B aligned for LDS.128).
   Epilogue folds the global min/max reduction. */
__global__ __launch_bounds__(256, 2) void k_gemm() {
    __shared__ float As[32][132];
    __shared__ float Bs[32][132];
    int k0 = blockIdx.x * 128;
    int n0 = blockIdx.y * 128;
    int tid = threadIdx.x;
    float acc[8][8];
    #pragma unroll
    for (int i = 0; i < 8; i++)
        #pragma unroll
        for (int j = 0; j < 8; j++) acc[i][j] = 0.0f;

    int ty = tid >> 4, tx = tid & 15;
    for (int d0 = 0; d0 < 128; d0 += 32) {
        /* float4 global loads, scalar transposed smem stores */
        #pragma unroll
        for (int i = 0; i < 4; i++) {
            int lin = tid + i * 256;          /* 1024 float4 per array */
            int m   = lin >> 3;
            int dq  = lin & 7;
            float4 av = *(const float4*)&g_xn[(size_t)(n0 + m) * 128 + d0 + dq * 4];
            float4 bv = *(const float4*)&g_cn[(size_t)(k0 + m) * 128 + d0 + dq * 4];
            As[dq * 4 + 0][m] = av.x; As[dq * 4 + 1][m] = av.y;
            As[dq * 4 + 2][m] = av.z; As[dq * 4 + 3][m] = av.w;
            Bs[dq * 4 + 0][m] = bv.x; Bs[dq * 4 + 1][m] = bv.y;
            Bs[dq * 4 + 2][m] = bv.z; Bs[dq * 4 + 3][m] = bv.w;
        }
        __syncthreads();
        #pragma unroll
        for (int dd = 0; dd < 32; dd++) {
            float4 a0 = *(const float4*)&As[dd][ty * 8];
            float4 a1 = *(const float4*)&As[dd][ty * 8 + 4];
            float4 b0 = *(const float4*)&Bs[dd][tx * 4];
            float4 b1 = *(const float4*)&Bs[dd][64 + tx * 4];
            float ar[8] = {a0.x,a0.y,a0.z,a0.w,a1.x,a1.y,a1.z,a1.w};
            float br[8] = {b0.x,b0.y,b0.z,b0.w,b1.x,b1.y,b1.z,b1.w};
            #pragma unroll
            for (int i = 0; i < 8; i++)
                #pragma unroll
                for (int j = 0; j < 8; j++) acc[i][j] += ar[i] * br[j];
        }
        __syncthreads();
    }
    float mx = -3.4e38f, mn = 3.4e38f;
    #pragma unroll
    for (int i = 0; i < 8; i++) {
        size_t row = (size_t)(n0 + ty * 8 + i) * 1024;
        float4 v0 = {acc[i][0], acc[i][1], acc[i][2], acc[i][3]};
        float4 v1 = {acc[i][4], acc[i][5], acc[i][6], acc[i][7]};
        *(float4*)&g_cos[row + k0 + tx * 4]      = v0;
        *(float4*)&g_cos[row + k0 + 64 + tx * 4] = v1;
        #pragma unroll
        for (int j = 0; j < 8; j++) {
            mx = fmaxf(mx, acc[i][j]); mn = fminf(mn, acc[i][j]);
        }
    }
    #pragma unroll
    for (int off = 16; off; off >>= 1) {
        mx = fmaxf(mx, __shfl_xor_sync(0xFFFFFFFFu, mx, off));
        mn = fminf(mn, __shfl_xor_sync(0xFFFFFFFFu, mn, off));
    }
    __shared__ float smx[8], smn[8];
    if ((tid & 31) == 0) { smx[tid >> 5] = mx; smn[tid >> 5] = mn; }
    __syncthreads();
    if (tid == 0) {
        float bmx = smx[0], bmn = smn[0];
        for (int i = 1; i < 8; i++) { bmx = fmaxf(bmx, smx[i]); bmn = fminf(bmn, smn[i]); }
        atomicMax(&g_omax, ford(bmx));
        atomicMin(&g_omin, ford(bmn));
    }
}

/* u1[k] = sum_n E[n,k] ; recomputes E from cos (no E array) */
__global__ __launch_bounds__(256) void k_u1() {
    int t  = threadIdx.x;
    int r0 = blockIdx.x * 64;
    float mid, amp; midamp(mid, amp);
    double a0 = 0, a1 = 0, a2 = 0, a3 = 0;
    for (int r = 0; r < 64; r++) {
        const float* row = g_cos + (size_t)(r0 + r) * 1024;
        a0 += calcE(row[t],       mid, amp);
        a1 += calcE(row[t + 256], mid, amp);
        a2 += calcE(row[t + 512], mid, amp);
        a3 += calcE(row[t + 768], mid, amp);
    }
    atomicAdd(&g_u1[t],       a0);
    atomicAdd(&g_u1[t + 256], a1);
    atomicAdd(&g_u1[t + 512], a2);
    atomicAdd(&g_u1[t + 768], a3);
}

/* a[k] = 1/(K*u[k]) from selected u buffer */
__global__ void k_a(int sel) {
    int k = threadIdx.x;
    const double* u = (sel == 1) ? g_u1 : g_u2;
    g_a[k] = 1.0 / (1024.0 * u[k]);
}

/* fused column-normalize + next row-sum:
   per row: s = sum_k E*a, b = 1/(N*s), u_next[k] += E*b.  Single cos read. */
__global__ __launch_bounds__(256) void k_fused(int pass) {
    __shared__ double sa[1024];
    __shared__ double sred[8];
    __shared__ double sb;
    int tid = threadIdx.x;
    for (int i = tid; i < 1024; i += 256) sa[i] = g_a[i];
    __syncthreads();
    float mid, amp; midamp(mid, amp);
    int r0 = blockIdx.x * 64;
    int lane = tid & 31, warp = tid >> 5;
    double c0 = 0, c1 = 0, c2 = 0, c3 = 0;
    double w0 = sa[tid], w1 = sa[tid + 256], w2 = sa[tid + 512], w3 = sa[tid + 768];
    for (int r = 0; r < 64; r++) {
        const float* row = g_cos + (size_t)(r0 + r) * 1024;
        double e0 = calcE(row[tid],       mid, amp);
        double e1 = calcE(row[tid + 256], mid, amp);
        double e2 = calcE(row[tid + 512], mid, amp);
        double e3 = calcE(row[tid + 768], mid, amp);
        double s  = fma(e0, w0, fma(e1, w1, fma(e2, w2, e3 * w3)));
        #pragma unroll
        for (int off = 16; off; off >>= 1) s += __shfl_xor_sync(0xFFFFFFFFu, s, off);
        if (lane == 0) sred[warp] = s;
        __syncthreads();
        if (tid == 0) {
            double t = sred[0];
            for (int i = 1; i < 8; i++) t += sred[i];
            sb = 1.0 / (32768.0 * t);
        }
        __syncthreads();
        double b = sb;
        c0 = fma(e0, b, c0); c1 = fma(e1, b, c1);
        c2 = fma(e2, b, c2); c3 = fma(e3, b, c3);
    }
    double* dst = (pass == 1) ? g_u2 : g_u3;
    atomicAdd(&dst[tid],       c0);
    atomicAdd(&dst[tid + 256], c1);
    atomicAdd(&dst[tid + 512], c2);
    atomicAdd(&dst[tid + 768], c3);
}

/* afix[k] = round(log2(1/(K*u3_k)) * 2^20) */
__global__ void k_afix() {
    int k = threadIdx.x;
    double a = 1.0 / (1024.0 * g_u3[k]);
    g_afix[k] = llround(log2(a) * 1048576.0);
}

/* argmax in log2 fixed-point + fused per-row lse + loss. */
__global__ __launch_bounds__(256) void k_argmax() {
    __shared__ long long sA[1024];
    __shared__ double lpart[8];
    int tid = threadIdx.x;
    for (int i = tid; i < 1024; i += 256) sA[i] = g_afix[i];
    __syncthreads();
    int warp = tid >> 5, lane = tid & 31;
    float mid, amp; midamp(mid, amp);
    int n0 = blockIdx.x * 32 + warp * 4;
    double lsum = 0.0;
    for (int r = 0; r < 4; r++) {
        int n = n0 + r;
        const float* row = g_cos + (size_t)n * 1024;
        long long bkey = 0x8000000000000000LL;
        int bk = 0;
        float c[32];
        float cmx = -3.4e38f;
        #pragma unroll 8
        for (int j = 0; j < 32; j++) {
            int k = lane + j * 32;
            float cv = row[k];
            c[j] = cv;
            cmx = fmaxf(cmx, cv);
            float hi, lo;
            t2_split(cv, mid, amp, hi, lo);
            long long key = __float2ll_rn(hi * 1048576.0f)
                          + __float2ll_rn(lo * 1048576.0f)
                          + sA[k];
            if (key > bkey) { bkey = key; bk = k; }
        }
        #pragma unroll
        for (int off = 16; off; off >>= 1) {
            long long ov = __shfl_down_sync(0xFFFFFFFFu, bkey, off);
            int       ok = __shfl_down_sync(0xFFFFFFFFu, bk,   off);
            if (ov > bkey || (ov == bkey && ok < bk)) { bkey = ov; bk = ok; }
        }
        bk = __shfl_sync(0xFFFFFFFFu, bk, 0);
        /* lse: m = rowmax/0.2, s = sum exp(c/0.2 - m) */
        #pragma unroll
        for (int off = 16; off; off >>= 1)
            cmx = fmaxf(cmx, __shfl_xor_sync(0xFFFFFFFFu, cmx, off));
        float m = cmx / 0.2f;
        float s = 0.0f;
        #pragma unroll
        for (int j = 0; j < 32; j++) s += expf(c[j] / 0.2f - m);
        #pragma unroll
        for (int off = 16; off; off >>= 1) s += __shfl_xor_sync(0xFFFFFFFFu, s, off);
        if (lane == 0) {
            g_idx[n] = bk;
            float lse = m + logf(s);
            float li  = row[bk] / 0.2f;
            lsum += (double)(lse - li);
        }
    }
    if (lane == 0) lpart[warp] = lsum;
    __syncthreads();
    if (tid == 0) {
        double t = 0.0;
        for (int i = 0; i < 8; i++) t += lpart[i];
        atomicAdd(&g_loss, t);
    }
}

/* out = [x_q (N*D) | loss (1) | indices (N)] as float32 */
__global__ void k_out(const float* __restrict__ codebook,
                      float* __restrict__ out, int out_size) {
    int i = blockIdx.x * blockDim.x + threadIdx.x;
    if (i >= out_size) return;
    if (i < ND) {
        int n = i >> 7;
        out[i] = codebook[(size_t)g_idx[n] * 128 + (i & 127)];
    } else if (i == ND) {
        out[i] = (float)(g_loss / 32768.0);
    } else {
        int j = i - ND - 1;
        out[i] = (j < N_PTS) ? (float)g_idx[j] : 0.0f;
    }
}

/* ---------------- launch ---------------------------------------------------- */
extern "C" void kernel_launch(void* const* d_in, const int* in_sizes, int n_in,
                              void* d_out, int out_size) {
    const float* x  = (const float*)d_in[0];
    const float* cb = (const float*)d_in[1];
    if (n_in >= 2 && in_sizes[0] == K_CB * D_DIM && in_sizes[1] == ND) {
        const float* t = x; x = cb; cb = t;
    }
    float* out = (float*)d_out;

    k_init<<<1, 1024>>>();
    k_norm<<<(K_CB * 32 + 255) / 256, 256>>>(cb, K_CB, 0);
    k_norm<<<(N_PTS * 32 + 255) / 256, 256>>>(x, N_PTS, 1);

    dim3 ggrid(K_CB / 128, N_PTS / 128);
    k_gemm<<<ggrid, 256>>>();

    k_u1<<<N_PTS / 64, 256>>>();       /* u1 (reads omin/omax internally) */
    k_a<<<1, 1024>>>(1);               /* a1 */
    k_fused<<<N_PTS / 64, 256>>>(1);   /* b1 + u2 */
    k_a<<<1, 1024>>>(2);               /* a2 */
    k_fused<<<N_PTS / 64, 256>>>(2);   /* b2 + u3 */
    k_afix<<<1, 1024>>>();

    k_argmax<<<N_PTS / 32, 256>>>();

    int ob = (out_size + 255) / 256;
    if (ob > 0) k_out<<<ob, 256>>>(cb, out, out_size);
}

// round 7
// speedup vs baseline: 1.5138x; 1.5138x over previous
#include <cuda_runtime.h>
#include <math.h>
#include <stdint.h>

#define N_PTS 32768
#define D_DIM 128
#define K_CB  1024
#define ND    (N_PTS*D_DIM)        /* 4194304  */
#define NK    ((size_t)N_PTS*K_CB) /* 33554432 */

/* ---------------- persistent device scratch (no allocs allowed) ------------- */
__device__ float     g_xn[ND];            /* normalized x          16 MB  */
__device__ float     g_cn[K_CB*D_DIM];    /* normalized codebook   512 KB */
__device__ float     g_cos[N_PTS*K_CB];   /* cosine sims           134 MB */
__device__ double    g_u1[K_CB];
__device__ double    g_u2[K_CB];
__device__ double    g_u3[K_CB];
__device__ double    g_a[K_CB];
__device__ double    g_b[N_PTS];
__device__ long long g_afix[K_CB];        /* log2(a3)*2^20 fixed point    */
__device__ unsigned  g_omin, g_omax;      /* ordered-uint encoded min/max */
__device__ float     g_mid, g_c1hi, g_c1lo; /* precomputed scale constants */
__device__ double    g_loss;
__device__ int       g_idx[N_PTS];

/* ---------------- helpers --------------------------------------------------- */
__device__ __forceinline__ unsigned ford(float f) {
    unsigned u = __float_as_uint(f);
    return (u & 0x80000000u) ? ~u : (u | 0x80000000u);
}
__device__ __forceinline__ float funord(unsigned u) {
    return (u & 0x80000000u) ? __uint_as_float(u ^ 0x80000000u)
                             : __uint_as_float(~u);
}

/* Cd = -log2(e)/0.005 */
#define CD_FULL (-288.53900817779268)

/* t2 = ((d - mid) / amp) * Cd  computed as  u * C1  with C1 = Cd/amp
   split into two floats.  hi+lo carries t2 to ~3e-8 abs. */
__device__ __forceinline__ void t2_of(float c, float mid, float c1hi, float c1lo,
                                      float& hi, float& lo) {
    float d  = fmaf(-c, 5.0f, 5.0f);
    float u  = d - mid;
    hi = u * c1hi;
    lo = fmaf(u, c1hi, -hi);
    lo = fmaf(u, c1lo, lo);
}

/* E = 2^t2 with zero fp64 arithmetic; ex2.approx rel err ~2.4e-7 */
__device__ __forceinline__ double calcE(float c, float mid, float c1hi, float c1lo) {
    float hi, lo;
    t2_of(c, mid, c1hi, c1lo, hi, lo);
    float big = hi + 12582912.0f;                 /* 2^23+2^22 round trick */
    int   nn  = __float_as_int(big) - __float_as_int(12582912.0f);
    float nnf = big - 12582912.0f;
    float f   = (hi - nnf) + lo;
    float p;
    asm("ex2.approx.f32 %0, %1;" : "=f"(p) : "f"(f));
    unsigned long long eb =
        ((unsigned long long)__float_as_uint(p) << 29) +
        ((unsigned long long)(unsigned)(896 + nn) << 52);
    return __longlong_as_double((long long)eb);
}

__device__ __forceinline__ long long keyof(float c, float mid, float c1hi, float c1lo) {
    float hi, lo;
    t2_of(c, mid, c1hi, c1lo, hi, lo);
    /* *2^20 is exact (power-of-two scale); quantize at 2^-20 */
    return __float2ll_rn(hi * 1048576.0f) + __float2ll_rn(lo * 1048576.0f);
}

/* ---------------- kernels --------------------------------------------------- */

__global__ void k_init() {
    int i = threadIdx.x;
    g_u1[i] = 0.0; g_u2[i] = 0.0; g_u3[i] = 0.0;
    if (i == 0) { g_omin = 0xFFFFFFFFu; g_omax = 0u; g_loss = 0.0; }
}

/* L2 normalize rows of length 128; one warp per row */
__global__ void k_norm(const float* __restrict__ in, int rows, int isX) {
    int w    = (blockIdx.x * blockDim.x + threadIdx.x) >> 5;
    int lane = threadIdx.x & 31;
    if (w >= rows) return;
    float* out = isX ? g_xn : g_cn;
    const float* r = in + (size_t)w * D_DIM;
    float v0 = r[lane], v1 = r[lane + 32], v2 = r[lane + 64], v3 = r[lane + 96];
    float s = v0 * v0 + v1 * v1 + v2 * v2 + v3 * v3;
    #pragma unroll
    for (int off = 16; off; off >>= 1) s += __shfl_xor_sync(0xFFFFFFFFu, s, off);
    float den = fmaxf(sqrtf(s), 1e-12f);
    float* o = out + (size_t)w * D_DIM;
    o[lane]      = v0 / den;
    o[lane + 32] = v1 / den;
    o[lane + 64] = v2 / den;
    o[lane + 96] = v3 / den;
}

/* cos GEMM — unchanged from the passing round-6 config (200us). */
__global__ __launch_bounds__(256, 2) void k_gemm() {
    __shared__ float As[32][132];
    __shared__ float Bs[32][132];
    int k0 = blockIdx.x * 128;
    int n0 = blockIdx.y * 128;
    int tid = threadIdx.x;
    float acc[8][8];
    #pragma unroll
    for (int i = 0; i < 8; i++)
        #pragma unroll
        for (int j = 0; j < 8; j++) acc[i][j] = 0.0f;

    int ty = tid >> 4, tx = tid & 15;
    for (int d0 = 0; d0 < 128; d0 += 32) {
        #pragma unroll
        for (int i = 0; i < 4; i++) {
            int lin = tid + i * 256;
            int m   = lin >> 3;
            int dq  = lin & 7;
            float4 av = *(const float4*)&g_xn[(size_t)(n0 + m) * 128 + d0 + dq * 4];
            float4 bv = *(const float4*)&g_cn[(size_t)(k0 + m) * 128 + d0 + dq * 4];
            As[dq * 4 + 0][m] = av.x; As[dq * 4 + 1][m] = av.y;
            As[dq * 4 + 2][m] = av.z; As[dq * 4 + 3][m] = av.w;
            Bs[dq * 4 + 0][m] = bv.x; Bs[dq * 4 + 1][m] = bv.y;
            Bs[dq * 4 + 2][m] = bv.z; Bs[dq * 4 + 3][m] = bv.w;
        }
        __syncthreads();
        #pragma unroll
        for (int dd = 0; dd < 32; dd++) {
            float4 a0 = *(const float4*)&As[dd][ty * 8];
            float4 a1 = *(const float4*)&As[dd][ty * 8 + 4];
            float4 b0 = *(const float4*)&Bs[dd][tx * 4];
            float4 b1 = *(const float4*)&Bs[dd][64 + tx * 4];
            float ar[8] = {a0.x,a0.y,a0.z,a0.w,a1.x,a1.y,a1.z,a1.w};
            float br[8] = {b0.x,b0.y,b0.z,b0.w,b1.x,b1.y,b1.z,b1.w};
            #pragma unroll
            for (int i = 0; i < 8; i++)
                #pragma unroll
                for (int j = 0; j < 8; j++) acc[i][j] += ar[i] * br[j];
        }
        __syncthreads();
    }
    float mx = -3.4e38f, mn = 3.4e38f;
    #pragma unroll
    for (int i = 0; i < 8; i++) {
        size_t row = (size_t)(n0 + ty * 8 + i) * 1024;
        float4 v0 = {acc[i][0], acc[i][1], acc[i][2], acc[i][3]};
        float4 v1 = {acc[i][4], acc[i][5], acc[i][6], acc[i][7]};
        *(float4*)&g_cos[row + k0 + tx * 4]      = v0;
        *(float4*)&g_cos[row + k0 + 64 + tx * 4] = v1;
        #pragma unroll
        for (int j = 0; j < 8; j++) {
            mx = fmaxf(mx, acc[i][j]); mn = fminf(mn, acc[i][j]);
        }
    }
    #pragma unroll
    for (int off = 16; off; off >>= 1) {
        mx = fmaxf(mx, __shfl_xor_sync(0xFFFFFFFFu, mx, off));
        mn = fminf(mn, __shfl_xor_sync(0xFFFFFFFFu, mn, off));
    }
    __shared__ float smx[8], smn[8];
    if ((tid & 31) == 0) { smx[tid >> 5] = mx; smn[tid >> 5] = mn; }
    __syncthreads();
    if (tid == 0) {
        float bmx = smx[0], bmn = smn[0];
        for (int i = 1; i < 8; i++) { bmx = fmaxf(bmx, smx[i]); bmn = fminf(bmn, smn[i]); }
        atomicMax(&g_omax, ford(bmx));
        atomicMin(&g_omin, ford(bmn));
    }
}

/* precompute mid and the split scale C1 = Cd/amp */
__global__ void k_pre() {
    float cmin = funord(g_omin), cmax = funord(g_omax);
    float dmax = fmaf(-cmin, 5.0f, 5.0f);
    float dmin = fmaf(-cmax, 5.0f, 5.0f);
    float mid  = (dmax + dmin) / 2.0f;
    float amp  = fmaxf(dmax - mid + 1e-5f, 1e-5f);
    double c1  = CD_FULL / (double)amp;
    float hi = (float)c1;
    g_mid = mid; g_c1hi = hi; g_c1lo = (float)(c1 - (double)hi);
}

/* u1[k] = sum_n E[n,k].  Thread t owns cols 4t..4t+3; float4 loads. */
__global__ __launch_bounds__(256) void k_u1() {
    int t  = threadIdx.x;
    int r0 = blockIdx.x * 64;
    float mid = g_mid, c1h = g_c1hi, c1l = g_c1lo;
    double a0 = 0, a1 = 0, a2 = 0, a3 = 0;
    #pragma unroll 4
    for (int r = 0; r < 64; r++) {
        float4 v = *(const float4*)(g_cos + (size_t)(r0 + r) * 1024 + 4 * t);
        a0 += calcE(v.x, mid, c1h, c1l);
        a1 += calcE(v.y, mid, c1h, c1l);
        a2 += calcE(v.z, mid, c1h, c1l);
        a3 += calcE(v.w, mid, c1h, c1l);
    }
    atomicAdd(&g_u1[4 * t + 0], a0);
    atomicAdd(&g_u1[4 * t + 1], a1);
    atomicAdd(&g_u1[4 * t + 2], a2);
    atomicAdd(&g_u1[4 * t + 3], a3);
}

/* a[k] = 1/(K*u[k]) */
__global__ void k_a(int sel) {
    int k = threadIdx.x;
    const double* u = (sel == 1) ? g_u1 : g_u2;
    g_a[k] = 1.0 / (1024.0 * u[k]);
}

/* b[n] = 1/(N * sum_k E[n,k]*a[k]); warp per row, shuffle-only reduce */
__global__ __launch_bounds__(256) void k_colsum() {
    __shared__ double sa[1024];
    int tid = threadIdx.x;
    for (int i = tid; i < 1024; i += 256) sa[i] = g_a[i];
    __syncthreads();
    int warp = tid >> 5, lane = tid & 31;
    float mid = g_mid, c1h = g_c1hi, c1l = g_c1lo;
    int n0 = blockIdx.x * 32 + warp * 4;
    for (int r = 0; r < 4; r++) {
        int n = n0 + r;
        const float4* row = (const float4*)(g_cos + (size_t)n * 1024);
        double s0 = 0, s1 = 0;
        #pragma unroll
        for (int j = 0; j < 8; j++) {
            float4 v = row[lane + 32 * j];
            int kb = 4 * lane + 128 * j;
            s0 = fma(calcE(v.x, mid, c1h, c1l), sa[kb + 0], s0);
            s1 = fma(calcE(v.y, mid, c1h, c1l), sa[kb + 1], s1);
            s0 = fma(calcE(v.z, mid, c1h, c1l), sa[kb + 2], s0);
            s1 = fma(calcE(v.w, mid, c1h, c1l), sa[kb + 3], s1);
        }
        double s = s0 + s1;
        #pragma unroll
        for (int off = 16; off; off >>= 1) s += __shfl_xor_sync(0xFFFFFFFFu, s, off);
        if (lane == 0) g_b[n] = 1.0 / (32768.0 * s);
    }
}

/* u[k] += sum_n E[n,k]*b[n]; col-strided, b preloaded to shared */
__global__ __launch_bounds__(256) void k_sumE(int pass) {
    __shared__ double sb[64];
    int t  = threadIdx.x;
    int r0 = blockIdx.x * 64;
    if (t < 64) sb[t] = g_b[r0 + t];
    __syncthreads();
    float mid = g_mid, c1h = g_c1hi, c1l = g_c1lo;
    double a0 = 0, a1 = 0, a2 = 0, a3 = 0;
    #pragma unroll 4
    for (int r = 0; r < 64; r++) {
        float4 v = *(const float4*)(g_cos + (size_t)(r0 + r) * 1024 + 4 * t);
        double w = sb[r];
        a0 = fma(calcE(v.x, mid, c1h, c1l), w, a0);
        a1 = fma(calcE(v.y, mid, c1h, c1l), w, a1);
        a2 = fma(calcE(v.z, mid, c1h, c1l), w, a2);
        a3 = fma(calcE(v.w, mid, c1h, c1l), w, a3);
    }
    double* dst = (pass == 1) ? g_u2 : g_u3;
    atomicAdd(&dst[4 * t + 0], a0);
    atomicAdd(&dst[4 * t + 1], a1);
    atomicAdd(&dst[4 * t + 2], a2);
    atomicAdd(&dst[4 * t + 3], a3);
}

/* afix[k] = round(log2(1/(K*u3_k)) * 2^20) */
__global__ void k_afix() {
    int k = threadIdx.x;
    double a = 1.0 / (1024.0 * g_u3[k]);
    g_afix[k] = llround(log2(a) * 1048576.0);
}

/* argmax in log2 fixed-point + fused per-row lse + loss; warp per row */
__global__ __launch_bounds__(256) void k_argmax() {
    __shared__ long long sA[1024];
    __shared__ double lpart[8];
    int tid = threadIdx.x;
    for (int i = tid; i < 1024; i += 256) sA[i] = g_afix[i];
    __syncthreads();
    int warp = tid >> 5, lane = tid & 31;
    float mid = g_mid, c1h = g_c1hi, c1l = g_c1lo;
    int n0 = blockIdx.x * 32 + warp * 4;
    double lsum = 0.0;
    for (int r = 0; r < 4; r++) {
        int n = n0 + r;
        const float4* row = (const float4*)(g_cos + (size_t)n * 1024);
        long long bkey = 0x8000000000000000LL;
        int bk = 0;
        float c[32];
        float cmx = -3.4e38f;
        #pragma unroll
        for (int j = 0; j < 8; j++) {
            float4 v = row[lane + 32 * j];
            int kb = 4 * lane + 128 * j;
            c[4*j+0] = v.x; c[4*j+1] = v.y; c[4*j+2] = v.z; c[4*j+3] = v.w;
            #pragma unroll
            for (int m = 0; m < 4; m++) {
                float cv = c[4*j+m];
                cmx = fmaxf(cmx, cv);
                long long key = keyof(cv, mid, c1h, c1l) + sA[kb + m];
                int kk = kb + m;
                if (key > bkey || (key == bkey && kk < bk)) { bkey = key; bk = kk; }
            }
        }
        #pragma unroll
        for (int off = 16; off; off >>= 1) {
            long long ov = __shfl_down_sync(0xFFFFFFFFu, bkey, off);
            int       ok = __shfl_down_sync(0xFFFFFFFFu, bk,   off);
            if (ov > bkey || (ov == bkey && ok < bk)) { bkey = ov; bk = ok; }
        }
        bk = __shfl_sync(0xFFFFFFFFu, bk, 0);
        #pragma unroll
        for (int off = 16; off; off >>= 1)
            cmx = fmaxf(cmx, __shfl_xor_sync(0xFFFFFFFFu, cmx, off));
        float s = 0.0f;
        #pragma unroll
        for (int j = 0; j < 32; j++) {
            float arg = (c[j] - cmx) * 7.2134752044448170f;  /* 5*log2(e) */
            float e; asm("ex2.approx.f32 %0, %1;" : "=f"(e) : "f"(arg));
            s += e;
        }
        #pragma unroll
        for (int off = 16; off; off >>= 1) s += __shfl_xor_sync(0xFFFFFFFFu, s, off);
        if (lane == 0) {
            g_idx[n] = bk;
            float m   = cmx * 5.0f;
            float lse = m + logf(s);
            float li  = c[0] * 0.0f; /* placeholder, real value below */
            li = ((const float*)row)[bk] * 5.0f;
            lsum += (double)(lse - li);
        }
    }
    if (lane == 0) lpart[warp] = lsum;
    __syncthreads();
    if (tid == 0) {
        double t = 0.0;
        for (int i = 0; i < 8; i++) t += lpart[i];
        atomicAdd(&g_loss, t);
    }
}

/* out = [x_q (N*D) | loss (1) | indices (N)] as float32 */
__global__ void k_out(const float* __restrict__ codebook,
                      float* __restrict__ out, int out_size) {
    int i = blockIdx.x * blockDim.x + threadIdx.x;
    if (i >= out_size) return;
    if (i < ND) {
        int n = i >> 7;
        out[i] = codebook[(size_t)g_idx[n] * 128 + (i & 127)];
    } else if (i == ND) {
        out[i] = (float)(g_loss / 32768.0);
    } else {
        int j = i - ND - 1;
        out[i] = (j < N_PTS) ? (float)g_idx[j] : 0.0f;
    }
}

/* ---------------- launch ---------------------------------------------------- */
extern "C" void kernel_launch(void* const* d_in, const int* in_sizes, int n_in,
                              void* d_out, int out_size) {
    const float* x  = (const float*)d_in[0];
    const float* cb = (const float*)d_in[1];
    if (n_in >= 2 && in_sizes[0] == K_CB * D_DIM && in_sizes[1] == ND) {
        const float* t = x; x = cb; cb = t;
    }
    float* out = (float*)d_out;

    k_init<<<1, 1024>>>();
    k_norm<<<(K_CB * 32 + 255) / 256, 256>>>(cb, K_CB, 0);
    k_norm<<<(N_PTS * 32 + 255) / 256, 256>>>(x, N_PTS, 1);

    dim3 ggrid(K_CB / 128, N_PTS / 128);
    k_gemm<<<ggrid, 256>>>();
    k_pre<<<1, 1>>>();

    k_u1<<<N_PTS / 64, 256>>>();
    k_a<<<1, 1024>>>(1);
    k_colsum<<<N_PTS / 32, 256>>>();   /* b1 */
    k_sumE<<<N_PTS / 64, 256>>>(1);    /* u2 */
    k_a<<<1, 1024>>>(2);
    k_colsum<<<N_PTS / 32, 256>>>();   /* b2 */
    k_sumE<<<N_PTS / 64, 256>>>(2);    /* u3 */
    k_afix<<<1, 1024>>>();

    k_argmax<<<N_PTS / 32, 256>>>();

    int ob = (out_size + 255) / 256;
    if (ob > 0) k_out<<<ob, 256>>>(cb, out, out_size);
}